// round 15
// baseline (speedup 1.0000x reference)
#include <cuda_runtime.h>

#define NB 4
#define NA 160000
#define NG 64
#define NBLK 74              // K1 blocks per batch image (74*4 = 296 = 2*148: one wave @occ2)
#define K1_STRIDE (NBLK*256) // 18944
#define NBLK9 33             // blocks 0..32: 9 anchors/thread; 33..73: 8  (33*9+41*8=625)

// Scratch (__device__ globals)
// g_best[i]: bits[0:31) = float bits of best (rounded) IoU; bit 31 = lowq flag.
// g_blockmax layout TRANSPOSED: [(b*NG + g)*NBLK + blk] -> column-contiguous.
__device__ unsigned g_best[NB * NA];
__device__ float    g_blockmax[NB * NG * NBLK];
__device__ unsigned g_colmax[NB * NG];     // float bits of per-column max

// Reference-exact IoU: same _rn sequence + __fdividef at every evaluation site
// => bit-identical per (anchor,gt) across all kernels. Equality tests
// (q == shigh for lowq, q == best for argmax) implement exactly the
// reference's  mq == highest_per_gt  and first-occurrence  jnp.argmax.
__device__ __forceinline__ float box_area(float4 b) {
    return __fmul_rn(__fadd_rn(b.z, -b.x), __fadd_rn(b.w, -b.y));
}

__device__ __forceinline__ float iou_pair(float4 a, float areaA, float4 g, float areaG) {
    float ltx = fmaxf(g.x, a.x);
    float lty = fmaxf(g.y, a.y);
    float rbx = fminf(g.z, a.z);
    float rby = fminf(g.w, a.w);
    float w = fmaxf(__fadd_rn(rbx, -ltx), 0.0f);
    float h = fmaxf(__fadd_rn(rby, -lty), 0.0f);
    float inter = __fmul_rn(w, h);
    float denom = __fadd_rn(__fadd_rn(areaA, areaG), -inter);
    return __fdividef(inter, denom);   // inter==0 -> exactly 0; denom>0 always
}

__device__ __forceinline__ unsigned warp_max_u32(unsigned v) {
    unsigned r;
    asm("redux.sync.max.u32 %0, %1, 0xffffffff;" : "=r"(r) : "r"(v));
    return r;
}

// ---------------------------------------------------------------------------
// K1: R9-proven full IoU pass (hot loop untouched). Only the blockmax store
// indexing changed (transposed layout).
// ---------------------------------------------------------------------------
template <int KA>
__device__ __forceinline__ void k1_body(
    const float4* __restrict__ anchors, int b, int blk, int tid,
    const float4* sg, const float* sga, unsigned int* smax)
{
    const int a0 = blk * 256 + tid;
    const int lane = tid & 31;

    float4 an[KA]; float areaA[KA]; float best[KA];
#pragma unroll
    for (int k = 0; k < KA; ++k) {
        int a = a0 + k * K1_STRIDE;
        an[k] = anchors[b * NA + a];
        areaA[k] = box_area(an[k]);
        best[k] = 0.0f;                // q >= 0: fmax chain == true max
    }

    float gown[2] = {0.0f, 0.0f};

#pragma unroll 2
    for (int g = 0; g < NG; ++g) {
        float4 gb = sg[g];
        float  ag = sga[g];

        float cmax = 0.0f;
#pragma unroll
        for (int k = 0; k < KA; ++k) {
            float q = iou_pair(an[k], areaA[k], gb, ag);
            cmax = fmaxf(cmax, q);
            best[k] = fmaxf(best[k], q);
        }

        unsigned wm = warp_max_u32(__float_as_uint(cmax));   // IoU>=0: uint order ok
        if (lane == (g & 31))
            gown[g >> 5] = __uint_as_float(wm);
    }

#pragma unroll
    for (int k = 0; k < KA; ++k) {
        int a = a0 + k * K1_STRIDE;
        g_best[b * NA + a] = __float_as_uint(best[k]);   // bit31 clear (best >= 0)
    }

    atomicMax(&smax[lane],      __float_as_uint(gown[0]));
    atomicMax(&smax[lane + 32], __float_as_uint(gown[1]));
}

__global__ __launch_bounds__(256, 2)
void k_main(const float4* __restrict__ anchors, const float4* __restrict__ gts)
{
    const int b = blockIdx.y;
    const int blk = blockIdx.x;
    const int tid = threadIdx.x;

    __shared__ float4 sg[NG];
    __shared__ float  sga[NG];
    __shared__ unsigned int smax[NG];

    if (tid < NG) {
        float4 g = gts[b * NG + tid];
        sg[tid] = g;
        sga[tid] = box_area(g);
        smax[tid] = 0u;
    }
    __syncthreads();

    if (blk < NBLK9) k1_body<9>(anchors, b, blk, tid, sg, sga, smax);
    else             k1_body<8>(anchors, b, blk, tid, sg, sga, smax);

    __syncthreads();
    if (tid < NG)   // transposed: column-contiguous for k_colmax
        g_blockmax[(b * NG + tid) * NBLK + blk] = __uint_as_float(smax[tid]);
}

// ---------------------------------------------------------------------------
// K2a: per-column max. Warp-per-column over contiguous 74 floats.
// 32 blocks x 8 warps = 256 warps = 256 columns.
// ---------------------------------------------------------------------------
__global__ __launch_bounds__(256)
void k_colmax()
{
    const int w = blockIdx.x * 8 + (threadIdx.x >> 5);   // column index 0..255
    const int lane = threadIdx.x & 31;

    const float* src = g_blockmax + w * NBLK;
    float m = fmaxf(src[lane], src[lane + 32]);
    if (lane + 64 < NBLK) m = fmaxf(m, src[lane + 64]);

    unsigned r = warp_max_u32(__float_as_uint(m));       // vals >= 0: uint order ok
    if (lane == 0) g_colmax[w] = r;
}

// ---------------------------------------------------------------------------
// K2b: distributed low-quality flagging. Block (blk,b) checks ITS OWN 64
// blockmax entries vs the column maxima; for each winning column it rescans
// only its own anchors and flags rounded-equality hits (bit 31 of g_best).
// ---------------------------------------------------------------------------
__global__ __launch_bounds__(256)
void k_fix(const float4* __restrict__ anchors, const float4* __restrict__ gts)
{
    const int blk = blockIdx.x;
    const int b   = blockIdx.y;
    const int tid = threadIdx.x;

    __shared__ float ssh[NG];
    __shared__ int   list[NG];
    __shared__ int   cnt;

    if (tid == 0) cnt = 0;
    __syncthreads();

    if (tid < NG) {
        float sh  = __uint_as_float(g_colmax[b * NG + tid]);
        float own = g_blockmax[(b * NG + tid) * NBLK + blk];
        ssh[tid] = sh;
        if (own == sh) {               // this block contains a column-max achiever
            int i = atomicAdd(&cnt, 1);
            list[i] = tid;
        }
    }
    __syncthreads();

    const int n = cnt;
    if (n == 0) return;

    for (int i = 0; i < n; ++i) {
        int g = list[i];
        float4 gb = gts[b * NG + g];
        float  ag = box_area(gb);
        float  sh = ssh[g];
#pragma unroll
        for (int k = 0; k < 9; ++k) {       // covers both 9- and 8-anchor blocks
            int a = blk * 256 + k * K1_STRIDE + tid;
            if (a < NA) {
                float4 an = anchors[b * NA + a];
                float v = iou_pair(an, box_area(an), gb, ag);
                if (v == sh)
                    atomicOr(&g_best[b * NA + a], 0x80000000u);
            }
        }
    }
}

// ---------------------------------------------------------------------------
// K3: R9-exact label + matched-box writer; sparse argmax recovery only for
// positive anchors (lowq flag or best >= 0.7).
// ---------------------------------------------------------------------------
__global__ __launch_bounds__(256)
void k_label(const float4* __restrict__ anchors,
             const float4* __restrict__ gts, const float* __restrict__ scores,
             const int* __restrict__ confs,
             float* __restrict__ outL, float4* __restrict__ outB)
{
    const int b = blockIdx.y;
    const int tid = threadIdx.x;

    __shared__ float4 sg[NG];
    __shared__ float  sga[NG];
    __shared__ float  ss[NG];
    __shared__ int    sc[NG];
    if (tid < NG) {
        float4 g = gts[b * NG + tid];
        sg[tid] = g;
        sga[tid] = box_area(g);
        ss[tid] = scores[b * NG + tid];
        sc[tid] = confs[b * NG + tid];
    }
    __syncthreads();

    const int a = blockIdx.x * 256 + tid;   // NA = 625*256 exactly
    const int idx = b * NA + a;

    unsigned bb = g_best[idx];
    bool lowq = (bb & 0x80000000u) != 0u;
    float best = __uint_as_float(bb & 0x7FFFFFFFu);
    bool pos = lowq || (best >= 0.7f);

    int bestg = 0;
    if (pos) {
        float4 an = anchors[idx];
        float areaA = box_area(an);
#pragma unroll 4
        for (int g = 0; g < NG; ++g) {
            if (iou_pair(an, areaA, sg[g], sga[g]) == best) { bestg = g; break; }
        }
    }

    // Matcher: positive -> bestg ; else <0.3 -> -1 ; else (0.3..0.7) -> -2.
    int midx = pos ? bestg : (best >= 0.3f ? -2 : -1);
    int cl = pos ? bestg : 0;

    float s = ss[cl];
    int c = sc[cl];
    float label = (midx == -1) ? 0.0f
                : (midx == -2) ? -1.0f
                : ((s < 1.0f || c == 0) ? -1.0f : 1.0f);

    outL[idx] = label;
    outB[idx] = sg[cl];
}

extern "C" void kernel_launch(void* const* d_in, const int* in_sizes, int n_in,
                              void* d_out, int out_size) {
    (void)in_sizes; (void)n_in; (void)out_size;
    const float4* anchors = (const float4*)d_in[0];   // [B, A, 4] f32
    const float4* gts     = (const float4*)d_in[1];   // [B, G, 4] f32
    const float*  scores  = (const float*)d_in[2];    // [B, G] f32
    const int*    confs   = (const int*)d_in[3];      // [B, G] i32

    float*  outL = (float*)d_out;                      // labels [B, A]
    float4* outB = (float4*)((float*)d_out + NB * NA); // matched boxes [B, A, 4]

    k_main  <<<dim3(NBLK, NB), 256>>>(anchors, gts);
    k_colmax<<<32, 256>>>();
    k_fix   <<<dim3(NBLK, NB), 256>>>(anchors, gts);
    k_label <<<dim3(NA / 256, NB), 256>>>(anchors, gts, scores, confs, outL, outB);
}